// round 10
// baseline (speedup 1.0000x reference)
#include <cuda_runtime.h>
#include <cuda_fp16.h>
#include <cstdint>

#define IN_F  4096
#define OUT_F 4096
#define BATCH 4096

// ---------------- scratch (device globals: sanctioned no-alloc path) -------
__device__ __half g_wh[(size_t)OUT_F * IN_F];   // W as exact-int fp16
__device__ __half g_xh[(size_t)BATCH * IN_F];   // x as fp16
__device__ float  g_rowsum[BATCH];
__device__ float  g_biasf[OUT_F];
__device__ int    g_wpart[2048 * 2];   // per-block W min/max partials

// ---------------- helpers ---------------------------------------------------
__device__ __forceinline__ uint32_t smem_u32(const void* p) {
    uint32_t a;
    asm("{ .reg .u64 t; cvta.to.shared.u64 t, %1; cvt.u32.u64 %0, t; }"
        : "=r"(a) : "l"(p));
    return a;
}
__device__ __forceinline__ uint32_t sw128(uint32_t o) { return o ^ ((o >> 3) & 0x70); }

#define CP_ASYNC16(dst_u32, src_ptr) \
    asm volatile("cp.async.cg.shared.global [%0], [%1], 16;" \
                 :: "r"(dst_u32), "l"(src_ptr) : "memory")
#define CP_COMMIT()   asm volatile("cp.async.commit_group;" ::: "memory")
#define CP_WAIT1()    asm volatile("cp.async.wait_group 1;" ::: "memory")

__device__ __forceinline__ void ldsm_x4(uint32_t& r0, uint32_t& r1,
                                        uint32_t& r2, uint32_t& r3,
                                        uint32_t addr) {
    asm volatile("ldmatrix.sync.aligned.m8n8.x4.shared.b16 {%0,%1,%2,%3}, [%4];"
                 : "=r"(r0), "=r"(r1), "=r"(r2), "=r"(r3) : "r"(addr));
}

__device__ __forceinline__ void mma_f16(float* c, const uint32_t* a,
                                        uint32_t b0, uint32_t b1) {
    asm volatile(
        "mma.sync.aligned.m16n8k16.row.col.f32.f16.f16.f32 "
        "{%0,%1,%2,%3}, {%4,%5,%6,%7}, {%8,%9}, {%0,%1,%2,%3};"
        : "+f"(c[0]), "+f"(c[1]), "+f"(c[2]), "+f"(c[3])
        : "r"(a[0]), "r"(a[1]), "r"(a[2]), "r"(a[3]), "r"(b0), "r"(b1));
}

// ---------------- fused preprocessing (single kernel) -----------------------
// blocks [0,2048)        : W minmax partials + int32 -> exact fp16
// blocks [2048,2048+4096): x -> fp16 + fp32 rowsum (one row per block)
// block  2048+4096       : bias minmax + dequant
#define PREPW_BLKS 2048

__global__ void k_prep(const int* __restrict__ wq,
                       const float* __restrict__ x,
                       const int* __restrict__ bq,
                       const float* __restrict__ pbmin,
                       const float* __restrict__ pbmax) {
    int bid = blockIdx.x;
    int tid = threadIdx.x;
    if (bid < PREPW_BLKS) {
        size_t n4 = (size_t)OUT_F * IN_F / 4;
        int lmin = 0x7fffffff, lmax = (int)0x80000000;
        for (size_t idx = bid * (size_t)blockDim.x + tid; idx < n4;
             idx += (size_t)PREPW_BLKS * blockDim.x) {
            int4 v = ((const int4*)wq)[idx];
            lmin = min(lmin, min(min(v.x, v.y), min(v.z, v.w)));
            lmax = max(lmax, max(max(v.x, v.y), max(v.z, v.w)));
            __half h[4];
            h[0] = __int2half_rn(v.x);
            h[1] = __int2half_rn(v.y);
            h[2] = __int2half_rn(v.z);
            h[3] = __int2half_rn(v.w);
            *((uint2*)&g_wh[idx * 4]) = *(uint2*)h;
        }
        __shared__ int smn[8], smx[8];
        for (int o = 16; o; o >>= 1) {
            lmin = min(lmin, __shfl_xor_sync(0xffffffffu, lmin, o));
            lmax = max(lmax, __shfl_xor_sync(0xffffffffu, lmax, o));
        }
        if ((tid & 31) == 0) { smn[tid >> 5] = lmin; smx[tid >> 5] = lmax; }
        __syncthreads();
        if (tid < 32) {
            int a = (tid < 8) ? smn[tid] : 0x7fffffff;
            int b = (tid < 8) ? smx[tid] : (int)0x80000000;
            for (int o = 4; o; o >>= 1) {
                a = min(a, __shfl_xor_sync(0xffffffffu, a, o));
                b = max(b, __shfl_xor_sync(0xffffffffu, b, o));
            }
            if (tid == 0) {
                g_wpart[bid * 2]     = a;
                g_wpart[bid * 2 + 1] = b;
            }
        }
    } else if (bid < PREPW_BLKS + BATCH) {
        int row = bid - PREPW_BLKS;
        const float4* xr = (const float4*)(x + (size_t)row * IN_F);
        float s = 0.f;
        for (int i4 = tid; i4 < IN_F / 4; i4 += blockDim.x) {
            float4 v = xr[i4];
            __half h[4];
            h[0] = __float2half_rn(v.x);
            h[1] = __float2half_rn(v.y);
            h[2] = __float2half_rn(v.z);
            h[3] = __float2half_rn(v.w);
            s += v.x + v.y + v.z + v.w;
            *((uint2*)&g_xh[(size_t)row * IN_F + i4 * 4]) = *(uint2*)h;
        }
        __shared__ float red[8];
        for (int o = 16; o; o >>= 1) s += __shfl_xor_sync(0xffffffffu, s, o);
        if ((tid & 31) == 0) red[tid >> 5] = s;
        __syncthreads();
        if (tid < 32) {
            float t = (tid < 8) ? red[tid] : 0.f;
            for (int o = 4; o; o >>= 1) t += __shfl_xor_sync(0xffffffffu, t, o);
            if (tid == 0) g_rowsum[row] = t;
        }
    } else {
        // bias: minmax + dequant, 256 threads x 16 elems
        __shared__ int redmn[8], redmx[8];
        int v[16];
        int lmin = 0x7fffffff, lmax = (int)0x80000000;
#pragma unroll
        for (int j = 0; j < 16; j++) {
            v[j] = bq[tid + j * 256];
            lmin = min(lmin, v[j]); lmax = max(lmax, v[j]);
        }
        for (int o = 16; o; o >>= 1) {
            lmin = min(lmin, __shfl_xor_sync(0xffffffffu, lmin, o));
            lmax = max(lmax, __shfl_xor_sync(0xffffffffu, lmax, o));
        }
        if ((tid & 31) == 0) { redmn[tid >> 5] = lmin; redmx[tid >> 5] = lmax; }
        __syncthreads();
        if (tid < 32) {
            int a = (tid < 8) ? redmn[tid] : 0x7fffffff;
            int b = (tid < 8) ? redmx[tid] : (int)0x80000000;
            for (int o = 4; o; o >>= 1) {
                a = min(a, __shfl_xor_sync(0xffffffffu, a, o));
                b = max(b, __shfl_xor_sync(0xffffffffu, b, o));
            }
            if (tid == 0) { redmn[0] = a; redmx[0] = b; }
        }
        __syncthreads();
        float bmn = *pbmin, bmx = *pbmax;
        float bsc = (bmx - bmn) / (float)(redmx[0] - redmn[0]);
        int qmn = redmn[0];
#pragma unroll
        for (int j = 0; j < 16; j++)
            g_biasf[tid + j * 256] = (float)(v[j] - qmn) * bsc + bmn;
    }
}

// ---- GEMM: 128 thr, 2x2 warps of 64x64, 3 stages, 1 barrier/chunk,
//      prefetch issued mid-compute (after ks=1) ------------------------------
#define TM 128
#define TN 128
#define KC 64                          // fp16 K elems per chunk (128B rows)
#define NSTAGE 3
#define NK (IN_F / KC)                 // 64 chunks
#define A_BYTES (TM * 128)             // 16 KB
#define STAGE_BYTES (A_BYTES * 2)      // 32 KB
#define SMEM_TOTAL (NSTAGE * STAGE_BYTES)   // 96 KB -> 2 CTAs/SM

__device__ __forceinline__ void load_chunk(int k, uint32_t sa, uint32_t sb,
                                           int m0, int n0, int tid) {
    int kk = k * KC;
#pragma unroll
    for (int j = 0; j < 8; j++) {          // A tile: 128 rows x 128B
        int u = tid + 128 * j;
        int row = u >> 3, seg = u & 7;
        const void* src = g_xh + (size_t)(m0 + row) * IN_F + kk + seg * 8;
        CP_ASYNC16(sa + sw128((uint32_t)(row * 128 + seg * 16)), src);
    }
#pragma unroll
    for (int j = 0; j < 8; j++) {          // B tile: 128 rows x 128B
        int u = tid + 128 * j;
        int row = u >> 3, seg = u & 7;
        const void* src = g_wh + (size_t)(n0 + row) * IN_F + kk + seg * 8;
        CP_ASYNC16(sb + sw128((uint32_t)(row * 128 + seg * 16)), src);
    }
}

__global__ void __launch_bounds__(128, 2) k_gemm(
    float* __restrict__ out,
    const float* __restrict__ p_wmin, const float* __restrict__ p_wmax) {
    extern __shared__ __align__(1024) char smem[];
    uint32_t sbase = smem_u32(smem);
    const int tid = threadIdx.x;
    const int wid = tid >> 5;
    const int lid = tid & 31;
    const int wm = wid >> 1;         // 2 warps along M -> 64-row warp tile
    const int wn = wid & 1;          // 2 warps along N -> 64-col warp tile
    const int m0 = blockIdx.y * TM;
    const int n0 = blockIdx.x * TN;

    float acc[4][8][4];
#pragma unroll
    for (int i = 0; i < 4; i++)
#pragma unroll
        for (int j = 0; j < 8; j++)
#pragma unroll
            for (int e = 0; e < 4; e++) acc[i][j][e] = 0.f;

    // prologue: fill stages 0 and 1 only (stage 2 stays free)
#pragma unroll
    for (int s = 0; s < 2; s++) {
        uint32_t sa = sbase + s * STAGE_BYTES;
        load_chunk(s, sa, sa + A_BYTES, m0, n0, tid);
        CP_COMMIT();
    }

    const int rlane = lid & 15;
    const int chalf = (lid >> 4) << 4;

    // chunk k lives in stage k%3; stage (k+2)%3 == (k-1)%3 is freed by the
    // barrier at the top of iteration k (all warps past compute of k-1).
    // Prefetch for k+2 is issued mid-compute (after ks=1): first LDSMs fire
    // immediately post-barrier, and the cp.async burst overlaps the MMA drain.
    for (int k = 0; k < NK; k++) {
        CP_WAIT1();                  // chunk k arrived (<=1 group pending)
        __syncthreads();             // all warps done computing chunk k-1
        uint32_t sa = sbase + (k % NSTAGE) * STAGE_BYTES;
        uint32_t sb = sa + A_BYTES;

#pragma unroll
        for (int ks = 0; ks < 4; ks++) {
            uint32_t a[4][4], b[4][4];
#pragma unroll
            for (int mi = 0; mi < 4; mi++) {
                int row = wm * 64 + mi * 16 + rlane;
                ldsm_x4(a[mi][0], a[mi][1], a[mi][2], a[mi][3],
                        sa + sw128((uint32_t)(row * 128 + ks * 32 + chalf)));
            }
#pragma unroll
            for (int ng = 0; ng < 4; ng++) {
                int row = wn * 64 + ng * 16 + rlane;
                ldsm_x4(b[ng][0], b[ng][1], b[ng][2], b[ng][3],
                        sb + sw128((uint32_t)(row * 128 + ks * 32 + chalf)));
            }
#pragma unroll
            for (int mi = 0; mi < 4; mi++)
#pragma unroll
                for (int ng = 0; ng < 4; ng++) {
                    mma_f16(acc[mi][ng * 2 + 0], a[mi], b[ng][0], b[ng][2]);
                    mma_f16(acc[mi][ng * 2 + 1], a[mi], b[ng][1], b[ng][3]);
                }
            if (ks == 1) {
                int kp = k + 2;
                if (kp < NK) {
                    uint32_t pa = sbase + (kp % NSTAGE) * STAGE_BYTES;
                    load_chunk(kp, pa, pa + A_BYTES, m0, n0, tid);
                }
                CP_COMMIT();         // unconditional: group count stays fixed
            }
        }
    }

    // ---- epilogue ---------------------------------------------------------
    // reduce W min/max partials (L2-hot, 2048 pairs) inside this CTA
    __shared__ float s_ws, s_alpha0;
    {
        int lmin = 0x7fffffff, lmax = (int)0x80000000;
#pragma unroll
        for (int j = 0; j < 16; j++) {
            int p = tid + j * 128;
            lmin = min(lmin, g_wpart[p * 2]);
            lmax = max(lmax, g_wpart[p * 2 + 1]);
        }
        __shared__ int redmn[4], redmx[4];
        for (int o = 16; o; o >>= 1) {
            lmin = min(lmin, __shfl_xor_sync(0xffffffffu, lmin, o));
            lmax = max(lmax, __shfl_xor_sync(0xffffffffu, lmax, o));
        }
        if ((tid & 31) == 0) { redmn[tid >> 5] = lmin; redmx[tid >> 5] = lmax; }
        __syncthreads();
        if (tid == 0) {
            int a = redmn[0], b = redmx[0];
#pragma unroll
            for (int j = 1; j < 4; j++) {
                a = min(a, redmn[j]); b = max(b, redmx[j]);
            }
            float wmn = *p_wmin, wmx = *p_wmax;
            float ws = (wmx - wmn) / (float)(b - a);
            s_ws = ws;
            s_alpha0 = wmn - ws * (float)a;
        }
        __syncthreads();
    }
    const float ws = s_ws, alpha0 = s_alpha0;

    const int rm = m0 + wm * 64;
    const int cn = n0 + wn * 64;
    float fb[16];
#pragma unroll
    for (int jn = 0; jn < 8; jn++) {
        int col = cn + jn * 8 + (lid & 3) * 2;
        float2 b2 = *(const float2*)&g_biasf[col];
        fb[jn * 2] = b2.x; fb[jn * 2 + 1] = b2.y;
    }
#pragma unroll
    for (int mi = 0; mi < 4; mi++) {
        int r0 = rm + mi * 16 + (lid >> 2);
        float radd0 = alpha0 * g_rowsum[r0];
        float radd1 = alpha0 * g_rowsum[r0 + 8];
#pragma unroll
        for (int jn = 0; jn < 8; jn++) {
            int col = cn + jn * 8 + (lid & 3) * 2;
            const float* c = acc[mi][jn];
            float2 o0, o1;
            o0.x = ws * c[0] + radd0 + fb[jn * 2];
            o0.y = ws * c[1] + radd0 + fb[jn * 2 + 1];
            o1.x = ws * c[2] + radd1 + fb[jn * 2];
            o1.y = ws * c[3] + radd1 + fb[jn * 2 + 1];
            *(float2*)&out[(size_t)r0 * OUT_F + col] = o0;
            *(float2*)&out[(size_t)(r0 + 8) * OUT_F + col] = o1;
        }
    }
}

// ---------------- launch ----------------------------------------------------
extern "C" void kernel_launch(void* const* d_in, const int* in_sizes, int n_in,
                              void* d_out, int out_size) {
    const float* x    = (const float*)d_in[0];
    const int*   wq   = (const int*)d_in[1];
    const int*   bq   = (const int*)d_in[2];
    const float* wmin = (const float*)d_in[3];
    const float* wmax = (const float*)d_in[4];
    const float* bmin = (const float*)d_in[5];
    const float* bmax = (const float*)d_in[6];
    float* out = (float*)d_out;

    cudaFuncSetAttribute(k_gemm, cudaFuncAttributeMaxDynamicSharedMemorySize,
                         SMEM_TOTAL);

    k_prep<<<PREPW_BLKS + BATCH + 1, 256>>>(wq, x, bq, bmin, bmax);  // launch 1
    dim3 grid(OUT_F / TN, BATCH / TM);
    k_gemm<<<grid, 128, SMEM_TOTAL>>>(out, wmin, wmax);              // launch 2
}

// round 11
// speedup vs baseline: 1.0181x; 1.0181x over previous
#include <cuda_runtime.h>
#include <cuda_fp16.h>
#include <cstdint>

#define IN_F  4096
#define OUT_F 4096
#define BATCH 4096

// ---------------- scratch (device globals: sanctioned no-alloc path) -------
__device__ __half  g_wh[(size_t)OUT_F * IN_F];   // W as exact-int fp16
__device__ __half  g_xh[(size_t)BATCH * IN_F];   // x as fp16
__device__ float   g_rowsum[BATCH];
__device__ float   g_biasf[OUT_F];
__device__ int     g_wpart[2048 * 2];   // per-block W min/max partials
__device__ float2  g_scale;             // {ws, alpha0}

// ---------------- helpers ---------------------------------------------------
__device__ __forceinline__ uint32_t smem_u32(const void* p) {
    uint32_t a;
    asm("{ .reg .u64 t; cvta.to.shared.u64 t, %1; cvt.u32.u64 %0, t; }"
        : "=r"(a) : "l"(p));
    return a;
}
__device__ __forceinline__ uint32_t sw128(uint32_t o) { return o ^ ((o >> 3) & 0x70); }

#define CP_ASYNC16(dst_u32, src_ptr) \
    asm volatile("cp.async.cg.shared.global [%0], [%1], 16;" \
                 :: "r"(dst_u32), "l"(src_ptr) : "memory")
#define CP_COMMIT()   asm volatile("cp.async.commit_group;" ::: "memory")
#define CP_WAIT2()    asm volatile("cp.async.wait_group 2;" ::: "memory")

__device__ __forceinline__ void ldsm_x4(uint32_t& r0, uint32_t& r1,
                                        uint32_t& r2, uint32_t& r3,
                                        uint32_t addr) {
    asm volatile("ldmatrix.sync.aligned.m8n8.x4.shared.b16 {%0,%1,%2,%3}, [%4];"
                 : "=r"(r0), "=r"(r1), "=r"(r2), "=r"(r3) : "r"(addr));
}

__device__ __forceinline__ void mma_f16(float* c, const uint32_t* a,
                                        uint32_t b0, uint32_t b1) {
    asm volatile(
        "mma.sync.aligned.m16n8k16.row.col.f32.f16.f16.f32 "
        "{%0,%1,%2,%3}, {%4,%5,%6,%7}, {%8,%9}, {%0,%1,%2,%3};"
        : "+f"(c[0]), "+f"(c[1]), "+f"(c[2]), "+f"(c[3])
        : "r"(a[0]), "r"(a[1]), "r"(a[2]), "r"(a[3]), "r"(b0), "r"(b1));
}

// ---------------- fused preprocessing (single kernel) -----------------------
// blocks [0,2048)        : W minmax partials + int32 -> exact fp16
// blocks [2048,2048+4096): x -> fp16 + fp32 rowsum (one row per block)
// block  2048+4096       : bias minmax + dequant
#define PREPW_BLKS 2048

__global__ void k_prep(const int* __restrict__ wq,
                       const float* __restrict__ x,
                       const int* __restrict__ bq,
                       const float* __restrict__ pbmin,
                       const float* __restrict__ pbmax) {
    int bid = blockIdx.x;
    int tid = threadIdx.x;
    if (bid < PREPW_BLKS) {
        size_t n4 = (size_t)OUT_F * IN_F / 4;
        int lmin = 0x7fffffff, lmax = (int)0x80000000;
        for (size_t idx = bid * (size_t)blockDim.x + tid; idx < n4;
             idx += (size_t)PREPW_BLKS * blockDim.x) {
            int4 v = ((const int4*)wq)[idx];
            lmin = min(lmin, min(min(v.x, v.y), min(v.z, v.w)));
            lmax = max(lmax, max(max(v.x, v.y), max(v.z, v.w)));
            __half h[4];
            h[0] = __int2half_rn(v.x);
            h[1] = __int2half_rn(v.y);
            h[2] = __int2half_rn(v.z);
            h[3] = __int2half_rn(v.w);
            *((uint2*)&g_wh[idx * 4]) = *(uint2*)h;
        }
        __shared__ int smn[8], smx[8];
        for (int o = 16; o; o >>= 1) {
            lmin = min(lmin, __shfl_xor_sync(0xffffffffu, lmin, o));
            lmax = max(lmax, __shfl_xor_sync(0xffffffffu, lmax, o));
        }
        if ((tid & 31) == 0) { smn[tid >> 5] = lmin; smx[tid >> 5] = lmax; }
        __syncthreads();
        if (tid < 32) {
            int a = (tid < 8) ? smn[tid] : 0x7fffffff;
            int b = (tid < 8) ? smx[tid] : (int)0x80000000;
            for (int o = 4; o; o >>= 1) {
                a = min(a, __shfl_xor_sync(0xffffffffu, a, o));
                b = max(b, __shfl_xor_sync(0xffffffffu, b, o));
            }
            if (tid == 0) {
                g_wpart[bid * 2]     = a;
                g_wpart[bid * 2 + 1] = b;
            }
        }
    } else if (bid < PREPW_BLKS + BATCH) {
        int row = bid - PREPW_BLKS;
        const float4* xr = (const float4*)(x + (size_t)row * IN_F);
        float s = 0.f;
        for (int i4 = tid; i4 < IN_F / 4; i4 += blockDim.x) {
            float4 v = xr[i4];
            __half h[4];
            h[0] = __float2half_rn(v.x);
            h[1] = __float2half_rn(v.y);
            h[2] = __float2half_rn(v.z);
            h[3] = __float2half_rn(v.w);
            s += v.x + v.y + v.z + v.w;
            *((uint2*)&g_xh[(size_t)row * IN_F + i4 * 4]) = *(uint2*)h;
        }
        __shared__ float red[8];
        for (int o = 16; o; o >>= 1) s += __shfl_xor_sync(0xffffffffu, s, o);
        if ((tid & 31) == 0) red[tid >> 5] = s;
        __syncthreads();
        if (tid < 32) {
            float t = (tid < 8) ? red[tid] : 0.f;
            for (int o = 4; o; o >>= 1) t += __shfl_xor_sync(0xffffffffu, t, o);
            if (tid == 0) g_rowsum[row] = t;
        }
    } else {
        // bias: minmax + dequant, 256 threads x 16 elems
        __shared__ int redmn[8], redmx[8];
        int v[16];
        int lmin = 0x7fffffff, lmax = (int)0x80000000;
#pragma unroll
        for (int j = 0; j < 16; j++) {
            v[j] = bq[tid + j * 256];
            lmin = min(lmin, v[j]); lmax = max(lmax, v[j]);
        }
        for (int o = 16; o; o >>= 1) {
            lmin = min(lmin, __shfl_xor_sync(0xffffffffu, lmin, o));
            lmax = max(lmax, __shfl_xor_sync(0xffffffffu, lmax, o));
        }
        if ((tid & 31) == 0) { redmn[tid >> 5] = lmin; redmx[tid >> 5] = lmax; }
        __syncthreads();
        if (tid < 32) {
            int a = (tid < 8) ? redmn[tid] : 0x7fffffff;
            int b = (tid < 8) ? redmx[tid] : (int)0x80000000;
            for (int o = 4; o; o >>= 1) {
                a = min(a, __shfl_xor_sync(0xffffffffu, a, o));
                b = max(b, __shfl_xor_sync(0xffffffffu, b, o));
            }
            if (tid == 0) { redmn[0] = a; redmx[0] = b; }
        }
        __syncthreads();
        float bmn = *pbmin, bmx = *pbmax;
        float bsc = (bmx - bmn) / (float)(redmx[0] - redmn[0]);
        int qmn = redmn[0];
#pragma unroll
        for (int j = 0; j < 16; j++)
            g_biasf[tid + j * 256] = (float)(v[j] - qmn) * bsc + bmn;
    }
}

// tiny: reduce W partials -> g_scale = {ws, alpha0}
__global__ void k_scale(const float* __restrict__ pwmin,
                        const float* __restrict__ pwmax) {
    __shared__ int redmn[8], redmx[8];
    int tid = threadIdx.x;   // 256 threads x 8 partials
    int lmin = 0x7fffffff, lmax = (int)0x80000000;
#pragma unroll
    for (int j = 0; j < 8; j++) {
        int p = tid + j * 256;
        lmin = min(lmin, g_wpart[p * 2]);
        lmax = max(lmax, g_wpart[p * 2 + 1]);
    }
    for (int o = 16; o; o >>= 1) {
        lmin = min(lmin, __shfl_xor_sync(0xffffffffu, lmin, o));
        lmax = max(lmax, __shfl_xor_sync(0xffffffffu, lmax, o));
    }
    if ((tid & 31) == 0) { redmn[tid >> 5] = lmin; redmx[tid >> 5] = lmax; }
    __syncthreads();
    if (tid == 0) {
        int a = redmn[0], b = redmx[0];
#pragma unroll
        for (int j = 1; j < 8; j++) {
            a = min(a, redmn[j]); b = max(b, redmx[j]);
        }
        float wmn = *pwmin, wmx = *pwmax;
        float ws = (wmx - wmn) / (float)(b - a);
        g_scale = make_float2(ws, wmn - ws * (float)a);
    }
}

// ---- GEMM: 128 thr, 2x2 warps of 64x64, 3 stages (R7 structure) ------------
#define TM 128
#define TN 128
#define KC 64                          // fp16 K elems per chunk (128B rows)
#define NSTAGE 3
#define NK (IN_F / KC)                 // 64 chunks
#define A_BYTES (TM * 128)             // 16 KB
#define STAGE_BYTES (A_BYTES * 2)      // 32 KB
#define SMEM_TOTAL (NSTAGE * STAGE_BYTES)   // 96 KB -> 2 CTAs/SM

__device__ __forceinline__ void load_chunk(int k, uint32_t sa, uint32_t sb,
                                           int m0, int n0, int tid) {
    int kk = k * KC;
#pragma unroll
    for (int j = 0; j < 8; j++) {          // A tile: 128 rows x 128B
        int u = tid + 128 * j;
        int row = u >> 3, seg = u & 7;
        const void* src = g_xh + (size_t)(m0 + row) * IN_F + kk + seg * 8;
        CP_ASYNC16(sa + sw128((uint32_t)(row * 128 + seg * 16)), src);
    }
#pragma unroll
    for (int j = 0; j < 8; j++) {          // B tile: 128 rows x 128B
        int u = tid + 128 * j;
        int row = u >> 3, seg = u & 7;
        const void* src = g_wh + (size_t)(n0 + row) * IN_F + kk + seg * 8;
        CP_ASYNC16(sb + sw128((uint32_t)(row * 128 + seg * 16)), src);
    }
}

__global__ void __launch_bounds__(128, 2) k_gemm(float* __restrict__ out) {
    extern __shared__ __align__(1024) char smem[];
    uint32_t sbase = smem_u32(smem);
    const int tid = threadIdx.x;
    const int wid = tid >> 5;
    const int lid = tid & 31;
    const int wm = wid >> 1;         // 2 warps along M -> 64-row warp tile
    const int wn = wid & 1;          // 2 warps along N -> 64-col warp tile
    const int m0 = blockIdx.y * TM;
    const int n0 = blockIdx.x * TN;

    float acc[4][8][4];
#pragma unroll
    for (int i = 0; i < 4; i++)
#pragma unroll
        for (int j = 0; j < 8; j++)
#pragma unroll
            for (int e = 0; e < 4; e++) acc[i][j][e] = 0.f;

    // prologue: fill all 3 stages
#pragma unroll
    for (int s = 0; s < NSTAGE; s++) {
        uint32_t sa = sbase + s * STAGE_BYTES;
        load_chunk(s, sa, sa + A_BYTES, m0, n0, tid);
        CP_COMMIT();
    }

    const int rlane = lid & 15;
    const int chalf = (lid >> 4) << 4;

#pragma unroll 3
    for (int k = 0; k < NK; k++) {
        CP_WAIT2();
        __syncthreads();
        uint32_t sa = sbase + (k % NSTAGE) * STAGE_BYTES;
        uint32_t sb = sa + A_BYTES;

#pragma unroll
        for (int ks = 0; ks < 4; ks++) {
            uint32_t a[4][4], b[4][4];
#pragma unroll
            for (int mi = 0; mi < 4; mi++) {
                int row = wm * 64 + mi * 16 + rlane;
                ldsm_x4(a[mi][0], a[mi][1], a[mi][2], a[mi][3],
                        sa + sw128((uint32_t)(row * 128 + ks * 32 + chalf)));
            }
#pragma unroll
            for (int ng = 0; ng < 4; ng++) {
                int row = wn * 64 + ng * 16 + rlane;
                ldsm_x4(b[ng][0], b[ng][1], b[ng][2], b[ng][3],
                        sb + sw128((uint32_t)(row * 128 + ks * 32 + chalf)));
            }
#pragma unroll
            for (int mi = 0; mi < 4; mi++)
#pragma unroll
                for (int ng = 0; ng < 4; ng++) {
                    mma_f16(acc[mi][ng * 2 + 0], a[mi], b[ng][0], b[ng][2]);
                    mma_f16(acc[mi][ng * 2 + 1], a[mi], b[ng][1], b[ng][3]);
                }
        }
        __syncthreads();
        if (k + NSTAGE < NK) {
            load_chunk(k + NSTAGE, sa, sb, m0, n0, tid);
        }
        CP_COMMIT();   // unconditional: pending-group count stays fixed
    }

    // ---- epilogue: fold scales, rowsum correction, bias -------------------
    const float2 sc = g_scale;
    const float ws = sc.x, alpha0 = sc.y;

    const int rm = m0 + wm * 64;
    const int cn = n0 + wn * 64;
    float fb[16];
#pragma unroll
    for (int jn = 0; jn < 8; jn++) {
        int col = cn + jn * 8 + (lid & 3) * 2;
        float2 b2 = *(const float2*)&g_biasf[col];
        fb[jn * 2] = b2.x; fb[jn * 2 + 1] = b2.y;
    }
#pragma unroll
    for (int mi = 0; mi < 4; mi++) {
        int r0 = rm + mi * 16 + (lid >> 2);
        float radd0 = alpha0 * g_rowsum[r0];
        float radd1 = alpha0 * g_rowsum[r0 + 8];
#pragma unroll
        for (int jn = 0; jn < 8; jn++) {
            int col = cn + jn * 8 + (lid & 3) * 2;
            const float* c = acc[mi][jn];
            float2 o0, o1;
            o0.x = ws * c[0] + radd0 + fb[jn * 2];
            o0.y = ws * c[1] + radd0 + fb[jn * 2 + 1];
            o1.x = ws * c[2] + radd1 + fb[jn * 2];
            o1.y = ws * c[3] + radd1 + fb[jn * 2 + 1];
            *(float2*)&out[(size_t)r0 * OUT_F + col] = o0;
            *(float2*)&out[(size_t)(r0 + 8) * OUT_F + col] = o1;
        }
    }
}

// ---------------- launch ----------------------------------------------------
extern "C" void kernel_launch(void* const* d_in, const int* in_sizes, int n_in,
                              void* d_out, int out_size) {
    const float* x    = (const float*)d_in[0];
    const int*   wq   = (const int*)d_in[1];
    const int*   bq   = (const int*)d_in[2];
    const float* wmin = (const float*)d_in[3];
    const float* wmax = (const float*)d_in[4];
    const float* bmin = (const float*)d_in[5];
    const float* bmax = (const float*)d_in[6];
    float* out = (float*)d_out;

    cudaFuncSetAttribute(k_gemm, cudaFuncAttributeMaxDynamicSharedMemorySize,
                         SMEM_TOTAL);

    k_prep<<<PREPW_BLKS + BATCH + 1, 256>>>(wq, x, bq, bmin, bmax);  // launch 1
    k_scale<<<1, 256>>>(wmin, wmax);                                 // launch 2
    dim3 grid(OUT_F / TN, BATCH / TM);
    k_gemm<<<grid, 128, SMEM_TOTAL>>>(out);                          // launch 3
}

// round 13
// speedup vs baseline: 1.0427x; 1.0241x over previous
#include <cuda_runtime.h>
#include <cuda_fp16.h>
#include <cstdint>

#define IN_F  4096
#define OUT_F 4096
#define BATCH 4096

// ---------------- scratch (device globals: sanctioned no-alloc path) -------
__device__ __half  g_wh[(size_t)OUT_F * IN_F];   // W as exact-int fp16
__device__ __half  g_xh[(size_t)BATCH * IN_F];   // x as fp16
__device__ float   g_rowsum[BATCH];
__device__ float   g_biasf[OUT_F];
__device__ int     g_wpart[2048 * 2];   // per-block W min/max partials
__device__ float2  g_scale;             // {ws, alpha0}

// ---------------- helpers ---------------------------------------------------
__device__ __forceinline__ uint32_t smem_u32(const void* p) {
    uint32_t a;
    asm("{ .reg .u64 t; cvta.to.shared.u64 t, %1; cvt.u32.u64 %0, t; }"
        : "=r"(a) : "l"(p));
    return a;
}
__device__ __forceinline__ uint32_t sw128(uint32_t o) { return o ^ ((o >> 3) & 0x70); }

#define CP_ASYNC16(dst_u32, src_ptr) \
    asm volatile("cp.async.cg.shared.global [%0], [%1], 16;" \
                 :: "r"(dst_u32), "l"(src_ptr) : "memory")
#define CP_COMMIT()   asm volatile("cp.async.commit_group;" ::: "memory")
#define CP_WAIT2()    asm volatile("cp.async.wait_group 2;" ::: "memory")

__device__ __forceinline__ void ldsm_x4(uint32_t& r0, uint32_t& r1,
                                        uint32_t& r2, uint32_t& r3,
                                        uint32_t addr) {
    asm volatile("ldmatrix.sync.aligned.m8n8.x4.shared.b16 {%0,%1,%2,%3}, [%4];"
                 : "=r"(r0), "=r"(r1), "=r"(r2), "=r"(r3) : "r"(addr));
}

__device__ __forceinline__ void mma_f16(float* c, const uint32_t* a,
                                        uint32_t b0, uint32_t b1) {
    asm volatile(
        "mma.sync.aligned.m16n8k16.row.col.f32.f16.f16.f32 "
        "{%0,%1,%2,%3}, {%4,%5,%6,%7}, {%8,%9}, {%0,%1,%2,%3};"
        : "+f"(c[0]), "+f"(c[1]), "+f"(c[2]), "+f"(c[3])
        : "r"(a[0]), "r"(a[1]), "r"(a[2]), "r"(a[3]), "r"(b0), "r"(b1));
}

// ---------------- fused preprocessing (single kernel) -----------------------
// blocks [0,2048)        : W minmax partials + int32 -> exact fp16
// blocks [2048,2048+4096): x -> fp16 + fp32 rowsum (one row per block)
// block  2048+4096       : bias minmax + dequant
#define PREPW_BLKS 2048

__global__ void k_prep(const int* __restrict__ wq,
                       const float* __restrict__ x,
                       const int* __restrict__ bq,
                       const float* __restrict__ pbmin,
                       const float* __restrict__ pbmax) {
    int bid = blockIdx.x;
    int tid = threadIdx.x;
    if (bid < PREPW_BLKS) {
        size_t n4 = (size_t)OUT_F * IN_F / 4;
        int lmin = 0x7fffffff, lmax = (int)0x80000000;
        for (size_t idx = bid * (size_t)blockDim.x + tid; idx < n4;
             idx += (size_t)PREPW_BLKS * blockDim.x) {
            int4 v = ((const int4*)wq)[idx];
            lmin = min(lmin, min(min(v.x, v.y), min(v.z, v.w)));
            lmax = max(lmax, max(max(v.x, v.y), max(v.z, v.w)));
            __half h[4];
            h[0] = __int2half_rn(v.x);
            h[1] = __int2half_rn(v.y);
            h[2] = __int2half_rn(v.z);
            h[3] = __int2half_rn(v.w);
            *((uint2*)&g_wh[idx * 4]) = *(uint2*)h;
        }
        __shared__ int smn[8], smx[8];
        for (int o = 16; o; o >>= 1) {
            lmin = min(lmin, __shfl_xor_sync(0xffffffffu, lmin, o));
            lmax = max(lmax, __shfl_xor_sync(0xffffffffu, lmax, o));
        }
        if ((tid & 31) == 0) { smn[tid >> 5] = lmin; smx[tid >> 5] = lmax; }
        __syncthreads();
        if (tid < 32) {
            int a = (tid < 8) ? smn[tid] : 0x7fffffff;
            int b = (tid < 8) ? smx[tid] : (int)0x80000000;
            for (int o = 4; o; o >>= 1) {
                a = min(a, __shfl_xor_sync(0xffffffffu, a, o));
                b = max(b, __shfl_xor_sync(0xffffffffu, b, o));
            }
            if (tid == 0) {
                g_wpart[bid * 2]     = a;
                g_wpart[bid * 2 + 1] = b;
            }
        }
    } else if (bid < PREPW_BLKS + BATCH) {
        int row = bid - PREPW_BLKS;
        const float4* xr = (const float4*)(x + (size_t)row * IN_F);
        float s = 0.f;
        for (int i4 = tid; i4 < IN_F / 4; i4 += blockDim.x) {
            float4 v = xr[i4];
            __half h[4];
            h[0] = __float2half_rn(v.x);
            h[1] = __float2half_rn(v.y);
            h[2] = __float2half_rn(v.z);
            h[3] = __float2half_rn(v.w);
            s += v.x + v.y + v.z + v.w;
            *((uint2*)&g_xh[(size_t)row * IN_F + i4 * 4]) = *(uint2*)h;
        }
        __shared__ float red[8];
        for (int o = 16; o; o >>= 1) s += __shfl_xor_sync(0xffffffffu, s, o);
        if ((tid & 31) == 0) red[tid >> 5] = s;
        __syncthreads();
        if (tid < 32) {
            float t = (tid < 8) ? red[tid] : 0.f;
            for (int o = 4; o; o >>= 1) t += __shfl_xor_sync(0xffffffffu, t, o);
            if (tid == 0) g_rowsum[row] = t;
        }
    } else {
        // bias: minmax + dequant, 256 threads x 16 elems
        __shared__ int redmn[8], redmx[8];
        int v[16];
        int lmin = 0x7fffffff, lmax = (int)0x80000000;
#pragma unroll
        for (int j = 0; j < 16; j++) {
            v[j] = bq[tid + j * 256];
            lmin = min(lmin, v[j]); lmax = max(lmax, v[j]);
        }
        for (int o = 16; o; o >>= 1) {
            lmin = min(lmin, __shfl_xor_sync(0xffffffffu, lmin, o));
            lmax = max(lmax, __shfl_xor_sync(0xffffffffu, lmax, o));
        }
        if ((tid & 31) == 0) { redmn[tid >> 5] = lmin; redmx[tid >> 5] = lmax; }
        __syncthreads();
        if (tid < 32) {
            int a = (tid < 8) ? redmn[tid] : 0x7fffffff;
            int b = (tid < 8) ? redmx[tid] : (int)0x80000000;
            for (int o = 4; o; o >>= 1) {
                a = min(a, __shfl_xor_sync(0xffffffffu, a, o));
                b = max(b, __shfl_xor_sync(0xffffffffu, b, o));
            }
            if (tid == 0) { redmn[0] = a; redmx[0] = b; }
        }
        __syncthreads();
        float bmn = *pbmin, bmx = *pbmax;
        float bsc = (bmx - bmn) / (float)(redmx[0] - redmn[0]);
        int qmn = redmn[0];
#pragma unroll
        for (int j = 0; j < 16; j++)
            g_biasf[tid + j * 256] = (float)(v[j] - qmn) * bsc + bmn;
    }
}

// tiny: reduce W partials -> g_scale = {ws, alpha0}
__global__ void k_scale(const float* __restrict__ pwmin,
                        const float* __restrict__ pwmax) {
    __shared__ int redmn[8], redmx[8];
    int tid = threadIdx.x;   // 256 threads x 8 partials
    int lmin = 0x7fffffff, lmax = (int)0x80000000;
#pragma unroll
    for (int j = 0; j < 8; j++) {
        int p = tid + j * 256;
        lmin = min(lmin, g_wpart[p * 2]);
        lmax = max(lmax, g_wpart[p * 2 + 1]);
    }
    for (int o = 16; o; o >>= 1) {
        lmin = min(lmin, __shfl_xor_sync(0xffffffffu, lmin, o));
        lmax = max(lmax, __shfl_xor_sync(0xffffffffu, lmax, o));
    }
    if ((tid & 31) == 0) { redmn[tid >> 5] = lmin; redmx[tid >> 5] = lmax; }
    __syncthreads();
    if (tid == 0) {
        int a = redmn[0], b = redmx[0];
#pragma unroll
        for (int j = 1; j < 8; j++) {
            a = min(a, redmn[j]); b = max(b, redmx[j]);
        }
        float wmn = *pwmin, wmx = *pwmax;
        float ws = (wmx - wmn) / (float)(b - a);
        g_scale = make_float2(ws, wmn - ws * (float)a);
    }
}

// ---- GEMM: 128 thr, 2x2 warps of 64x64, 3 stages (R7 structure, verbatim) --
#define TM 128
#define TN 128
#define KC 64                          // fp16 K elems per chunk (128B rows)
#define NSTAGE 3
#define NK (IN_F / KC)                 // 64 chunks
#define A_BYTES (TM * 128)             // 16 KB
#define STAGE_BYTES (A_BYTES * 2)      // 32 KB
#define SMEM_TOTAL (NSTAGE * STAGE_BYTES)   // 96 KB -> 2 CTAs/SM

__device__ __forceinline__ void load_chunk(int k, uint32_t sa, uint32_t sb,
                                           int m0, int n0, int tid) {
    int kk = k * KC;
#pragma unroll
    for (int j = 0; j < 8; j++) {          // A tile: 128 rows x 128B
        int u = tid + 128 * j;
        int row = u >> 3, seg = u & 7;
        const void* src = g_xh + (size_t)(m0 + row) * IN_F + kk + seg * 8;
        CP_ASYNC16(sa + sw128((uint32_t)(row * 128 + seg * 16)), src);
    }
#pragma unroll
    for (int j = 0; j < 8; j++) {          // B tile: 128 rows x 128B
        int u = tid + 128 * j;
        int row = u >> 3, seg = u & 7;
        const void* src = g_wh + (size_t)(n0 + row) * IN_F + kk + seg * 8;
        CP_ASYNC16(sb + sw128((uint32_t)(row * 128 + seg * 16)), src);
    }
}

__global__ void __launch_bounds__(128, 2) k_gemm(float* __restrict__ out) {
    extern __shared__ __align__(1024) char smem[];
    uint32_t sbase = smem_u32(smem);
    const int tid = threadIdx.x;
    const int wid = tid >> 5;
    const int lid = tid & 31;
    const int wm = wid >> 1;         // 2 warps along M -> 64-row warp tile
    const int wn = wid & 1;          // 2 warps along N -> 64-col warp tile
    const int m0 = blockIdx.y * TM;
    const int n0 = blockIdx.x * TN;

    float acc[4][8][4];
#pragma unroll
    for (int i = 0; i < 4; i++)
#pragma unroll
        for (int j = 0; j < 8; j++)
#pragma unroll
            for (int e = 0; e < 4; e++) acc[i][j][e] = 0.f;

    // prologue: fill all 3 stages
#pragma unroll
    for (int s = 0; s < NSTAGE; s++) {
        uint32_t sa = sbase + s * STAGE_BYTES;
        load_chunk(s, sa, sa + A_BYTES, m0, n0, tid);
        CP_COMMIT();
    }

    const int rlane = lid & 15;
    const int chalf = (lid >> 4) << 4;

    for (int k = 0; k < NK; k++) {
        CP_WAIT2();
        __syncthreads();
        uint32_t sa = sbase + (k % NSTAGE) * STAGE_BYTES;
        uint32_t sb = sa + A_BYTES;

#pragma unroll
        for (int ks = 0; ks < 4; ks++) {
            uint32_t a[4][4], b[4][4];
#pragma unroll
            for (int mi = 0; mi < 4; mi++) {
                int row = wm * 64 + mi * 16 + rlane;
                ldsm_x4(a[mi][0], a[mi][1], a[mi][2], a[mi][3],
                        sa + sw128((uint32_t)(row * 128 + ks * 32 + chalf)));
            }
#pragma unroll
            for (int ng = 0; ng < 4; ng++) {
                int row = wn * 64 + ng * 16 + rlane;
                ldsm_x4(b[ng][0], b[ng][1], b[ng][2], b[ng][3],
                        sb + sw128((uint32_t)(row * 128 + ks * 32 + chalf)));
            }
#pragma unroll
            for (int mi = 0; mi < 4; mi++)
#pragma unroll
                for (int ng = 0; ng < 4; ng++) {
                    mma_f16(acc[mi][ng * 2 + 0], a[mi], b[ng][0], b[ng][2]);
                    mma_f16(acc[mi][ng * 2 + 1], a[mi], b[ng][1], b[ng][3]);
                }
        }
        __syncthreads();
        if (k + NSTAGE < NK) {
            load_chunk(k + NSTAGE, sa, sb, m0, n0, tid);
        }
        CP_COMMIT();   // unconditional: pending-group count stays fixed
    }

    // ---- epilogue: fold scales, rowsum correction, bias -------------------
    const float2 sc = g_scale;
    const float ws = sc.x, alpha0 = sc.y;

    const int rm = m0 + wm * 64;
    const int cn = n0 + wn * 64;
    float fb[16];
#pragma unroll
    for (int jn = 0; jn < 8; jn++) {
        int col = cn + jn * 8 + (lid & 3) * 2;
        float2 b2 = *(const float2*)&g_biasf[col];
        fb[jn * 2] = b2.x; fb[jn * 2 + 1] = b2.y;
    }
#pragma unroll
    for (int mi = 0; mi < 4; mi++) {
        int r0 = rm + mi * 16 + (lid >> 2);
        float radd0 = alpha0 * g_rowsum[r0];
        float radd1 = alpha0 * g_rowsum[r0 + 8];
#pragma unroll
        for (int jn = 0; jn < 8; jn++) {
            int col = cn + jn * 8 + (lid & 3) * 2;
            const float* c = acc[mi][jn];
            float2 o0, o1;
            o0.x = ws * c[0] + radd0 + fb[jn * 2];
            o0.y = ws * c[1] + radd0 + fb[jn * 2 + 1];
            o1.x = ws * c[2] + radd1 + fb[jn * 2];
            o1.y = ws * c[3] + radd1 + fb[jn * 2 + 1];
            *(float2*)&out[(size_t)r0 * OUT_F + col] = o0;
            *(float2*)&out[(size_t)(r0 + 8) * OUT_F + col] = o1;
        }
    }
}

// ---------------- launch ----------------------------------------------------
extern "C" void kernel_launch(void* const* d_in, const int* in_sizes, int n_in,
                              void* d_out, int out_size) {
    const float* x    = (const float*)d_in[0];
    const int*   wq   = (const int*)d_in[1];
    const int*   bq   = (const int*)d_in[2];
    const float* wmin = (const float*)d_in[3];
    const float* wmax = (const float*)d_in[4];
    const float* bmin = (const float*)d_in[5];
    const float* bmax = (const float*)d_in[6];
    float* out = (float*)d_out;

    cudaFuncSetAttribute(k_gemm, cudaFuncAttributeMaxDynamicSharedMemorySize,
                         SMEM_TOTAL);

    k_prep<<<PREPW_BLKS + BATCH + 1, 256>>>(wq, x, bq, bmin, bmax);  // launch 1
    k_scale<<<1, 256>>>(wmin, wmax);                                 // launch 2
    dim3 grid(OUT_F / TN, BATCH / TM);
    k_gemm<<<grid, 128, SMEM_TOTAL>>>(out);                          // launch 3
}

// round 15
// speedup vs baseline: 1.0609x; 1.0174x over previous
#include <cuda_runtime.h>
#include <cuda_fp16.h>
#include <cstdint>

#define IN_F  4096
#define OUT_F 4096
#define BATCH 4096

// ---------------- scratch (device globals: sanctioned no-alloc path) -------
__device__ __half  g_wh[(size_t)OUT_F * IN_F];   // W as exact-int fp16
__device__ __half  g_xh[(size_t)BATCH * IN_F];   // x as fp16
__device__ float   g_rowsum[BATCH];
__device__ float   g_biasf[OUT_F];
__device__ int     g_wpart[2048 * 2];   // per-block W min/max partials
__device__ int     g_wctr;              // W-block completion counter (reset by finisher)
__device__ float2  g_scale;             // {ws, alpha0}

// ---------------- helpers ---------------------------------------------------
__device__ __forceinline__ uint32_t smem_u32(const void* p) {
    uint32_t a;
    asm("{ .reg .u64 t; cvta.to.shared.u64 t, %1; cvt.u32.u64 %0, t; }"
        : "=r"(a) : "l"(p));
    return a;
}
__device__ __forceinline__ uint32_t sw128(uint32_t o) { return o ^ ((o >> 3) & 0x70); }

#define CP_ASYNC16(dst_u32, src_ptr) \
    asm volatile("cp.async.cg.shared.global [%0], [%1], 16;" \
                 :: "r"(dst_u32), "l"(src_ptr) : "memory")
#define CP_COMMIT()   asm volatile("cp.async.commit_group;" ::: "memory")
#define CP_WAIT2()    asm volatile("cp.async.wait_group 2;" ::: "memory")

__device__ __forceinline__ void ldsm_x4(uint32_t& r0, uint32_t& r1,
                                        uint32_t& r2, uint32_t& r3,
                                        uint32_t addr) {
    asm volatile("ldmatrix.sync.aligned.m8n8.x4.shared.b16 {%0,%1,%2,%3}, [%4];"
                 : "=r"(r0), "=r"(r1), "=r"(r2), "=r"(r3) : "r"(addr));
}

__device__ __forceinline__ void mma_f16(float* c, const uint32_t* a,
                                        uint32_t b0, uint32_t b1) {
    asm volatile(
        "mma.sync.aligned.m16n8k16.row.col.f32.f16.f16.f32 "
        "{%0,%1,%2,%3}, {%4,%5,%6,%7}, {%8,%9}, {%0,%1,%2,%3};"
        : "+f"(c[0]), "+f"(c[1]), "+f"(c[2]), "+f"(c[3])
        : "r"(a[0]), "r"(a[1]), "r"(a[2]), "r"(a[3]), "r"(b0), "r"(b1));
}

// ---------------- fused preprocessing (single kernel) -----------------------
// blocks [0,2048)        : W minmax partials + int32 -> exact fp16 (contiguous,
//                          8 unrolled LDG.128/thread); LAST finisher reduces
//                          partials -> g_scale and resets the counter
// blocks [2048,2048+4096): x -> fp16 + fp32 rowsum (one row per block, unrolled)
// block  2048+4096       : bias minmax + dequant
#define PREPW_BLKS 2048

__global__ void k_prep(const int* __restrict__ wq,
                       const float* __restrict__ x,
                       const int* __restrict__ bq,
                       const float* __restrict__ pwmin,
                       const float* __restrict__ pwmax,
                       const float* __restrict__ pbmin,
                       const float* __restrict__ pbmax) {
    int bid = blockIdx.x;
    int tid = threadIdx.x;
    if (bid < PREPW_BLKS) {
        // each W block: contiguous 2048 int4 (8192 ints); 8 int4 per thread
        const int4* base = (const int4*)wq + (size_t)bid * 2048;
        int4 v[8];
#pragma unroll
        for (int j = 0; j < 8; j++) v[j] = base[tid + 256 * j];

        int lmin = 0x7fffffff, lmax = (int)0x80000000;
        __half* wdst = g_wh + (size_t)bid * 8192;
#pragma unroll
        for (int j = 0; j < 8; j++) {
            lmin = min(lmin, min(min(v[j].x, v[j].y), min(v[j].z, v[j].w)));
            lmax = max(lmax, max(max(v[j].x, v[j].y), max(v[j].z, v[j].w)));
            __half h[4];
            h[0] = __int2half_rn(v[j].x);
            h[1] = __int2half_rn(v[j].y);
            h[2] = __int2half_rn(v[j].z);
            h[3] = __int2half_rn(v[j].w);
            *((uint2*)&wdst[(tid + 256 * j) * 4]) = *(uint2*)h;
        }
        __shared__ int smn[8], smx[8];
        for (int o = 16; o; o >>= 1) {
            lmin = min(lmin, __shfl_xor_sync(0xffffffffu, lmin, o));
            lmax = max(lmax, __shfl_xor_sync(0xffffffffu, lmax, o));
        }
        if ((tid & 31) == 0) { smn[tid >> 5] = lmin; smx[tid >> 5] = lmax; }
        __syncthreads();
        __shared__ int s_last;
        if (tid == 0) {
            int a = smn[0], b = smx[0];
#pragma unroll
            for (int j = 1; j < 8; j++) { a = min(a, smn[j]); b = max(b, smx[j]); }
            g_wpart[bid * 2]     = a;
            g_wpart[bid * 2 + 1] = b;
            __threadfence();
            int t = atomicAdd(&g_wctr, 1);
            s_last = (t == PREPW_BLKS - 1) ? 1 : 0;
        }
        __syncthreads();
        if (s_last) {
            // this block is the last W block to finish: reduce partials -> scale
            __threadfence();   // acquire: order partial reads after the atomic
            int rmn = 0x7fffffff, rmx = (int)0x80000000;
#pragma unroll
            for (int j = 0; j < 8; j++) {
                int p = tid + j * 256;
                rmn = min(rmn, g_wpart[p * 2]);
                rmx = max(rmx, g_wpart[p * 2 + 1]);
            }
            for (int o = 16; o; o >>= 1) {
                rmn = min(rmn, __shfl_xor_sync(0xffffffffu, rmn, o));
                rmx = max(rmx, __shfl_xor_sync(0xffffffffu, rmx, o));
            }
            if ((tid & 31) == 0) { smn[tid >> 5] = rmn; smx[tid >> 5] = rmx; }
            __syncthreads();
            if (tid == 0) {
                int a = smn[0], b = smx[0];
#pragma unroll
                for (int j = 1; j < 8; j++) { a = min(a, smn[j]); b = max(b, smx[j]); }
                float wmn = *pwmin, wmx = *pwmax;
                float ws = (wmx - wmn) / (float)(b - a);
                g_scale = make_float2(ws, wmn - ws * (float)a);
                g_wctr = 0;            // reset for next graph replay
            }
        }
    } else if (bid < PREPW_BLKS + BATCH) {
        int row = bid - PREPW_BLKS;
        const float4* xr = (const float4*)(x + (size_t)row * IN_F);
        float4 v[4];
#pragma unroll
        for (int j = 0; j < 4; j++) v[j] = xr[tid + 256 * j];
        float s = 0.f;
#pragma unroll
        for (int j = 0; j < 4; j++) {
            __half h[4];
            h[0] = __float2half_rn(v[j].x);
            h[1] = __float2half_rn(v[j].y);
            h[2] = __float2half_rn(v[j].z);
            h[3] = __float2half_rn(v[j].w);
            s += v[j].x + v[j].y + v[j].z + v[j].w;
            *((uint2*)&g_xh[(size_t)row * IN_F + (tid + 256 * j) * 4]) = *(uint2*)h;
        }
        __shared__ float red[8];
        for (int o = 16; o; o >>= 1) s += __shfl_xor_sync(0xffffffffu, s, o);
        if ((tid & 31) == 0) red[tid >> 5] = s;
        __syncthreads();
        if (tid < 32) {
            float t = (tid < 8) ? red[tid] : 0.f;
            for (int o = 4; o; o >>= 1) t += __shfl_xor_sync(0xffffffffu, t, o);
            if (tid == 0) g_rowsum[row] = t;
        }
    } else {
        // bias: minmax + dequant, 256 threads x 16 elems
        __shared__ int redmn[8], redmx[8];
        int v[16];
        int lmin = 0x7fffffff, lmax = (int)0x80000000;
#pragma unroll
        for (int j = 0; j < 16; j++) {
            v[j] = bq[tid + j * 256];
            lmin = min(lmin, v[j]); lmax = max(lmax, v[j]);
        }
        for (int o = 16; o; o >>= 1) {
            lmin = min(lmin, __shfl_xor_sync(0xffffffffu, lmin, o));
            lmax = max(lmax, __shfl_xor_sync(0xffffffffu, lmax, o));
        }
        if ((tid & 31) == 0) { redmn[tid >> 5] = lmin; redmx[tid >> 5] = lmax; }
        __syncthreads();
        if (tid < 32) {
            int a = (tid < 8) ? redmn[tid] : 0x7fffffff;
            int b = (tid < 8) ? redmx[tid] : (int)0x80000000;
            for (int o = 4; o; o >>= 1) {
                a = min(a, __shfl_xor_sync(0xffffffffu, a, o));
                b = max(b, __shfl_xor_sync(0xffffffffu, b, o));
            }
            if (tid == 0) { redmn[0] = a; redmx[0] = b; }
        }
        __syncthreads();
        float bmn = *pbmin, bmx = *pbmax;
        float bsc = (bmx - bmn) / (float)(redmx[0] - redmn[0]);
        int qmn = redmn[0];
#pragma unroll
        for (int j = 0; j < 16; j++)
            g_biasf[tid + j * 256] = (float)(v[j] - qmn) * bsc + bmn;
    }
}

// ---- GEMM: 128 thr, 2x2 warps of 64x64, 3 stages (R13 best, verbatim) ------
#define TM 128
#define TN 128
#define KC 64                          // fp16 K elems per chunk (128B rows)
#define NSTAGE 3
#define NK (IN_F / KC)                 // 64 chunks
#define A_BYTES (TM * 128)             // 16 KB
#define STAGE_BYTES (A_BYTES * 2)      // 32 KB
#define SMEM_TOTAL (NSTAGE * STAGE_BYTES)   // 96 KB -> 2 CTAs/SM

__device__ __forceinline__ void load_chunk(int k, uint32_t sa, uint32_t sb,
                                           int m0, int n0, int tid) {
    int kk = k * KC;
#pragma unroll
    for (int j = 0; j < 8; j++) {          // A tile: 128 rows x 128B
        int u = tid + 128 * j;
        int row = u >> 3, seg = u & 7;
        const void* src = g_xh + (size_t)(m0 + row) * IN_F + kk + seg * 8;
        CP_ASYNC16(sa + sw128((uint32_t)(row * 128 + seg * 16)), src);
    }
#pragma unroll
    for (int j = 0; j < 8; j++) {          // B tile: 128 rows x 128B
        int u = tid + 128 * j;
        int row = u >> 3, seg = u & 7;
        const void* src = g_wh + (size_t)(n0 + row) * IN_F + kk + seg * 8;
        CP_ASYNC16(sb + sw128((uint32_t)(row * 128 + seg * 16)), src);
    }
}

__global__ void __launch_bounds__(128, 2) k_gemm(float* __restrict__ out) {
    extern __shared__ __align__(1024) char smem[];
    uint32_t sbase = smem_u32(smem);
    const int tid = threadIdx.x;
    const int wid = tid >> 5;
    const int lid = tid & 31;
    const int wm = wid >> 1;         // 2 warps along M -> 64-row warp tile
    const int wn = wid & 1;          // 2 warps along N -> 64-col warp tile
    const int m0 = blockIdx.y * TM;
    const int n0 = blockIdx.x * TN;

    float acc[4][8][4];
#pragma unroll
    for (int i = 0; i < 4; i++)
#pragma unroll
        for (int j = 0; j < 8; j++)
#pragma unroll
            for (int e = 0; e < 4; e++) acc[i][j][e] = 0.f;

    // prologue: fill all 3 stages
#pragma unroll
    for (int s = 0; s < NSTAGE; s++) {
        uint32_t sa = sbase + s * STAGE_BYTES;
        load_chunk(s, sa, sa + A_BYTES, m0, n0, tid);
        CP_COMMIT();
    }

    const int rlane = lid & 15;
    const int chalf = (lid >> 4) << 4;

    for (int k = 0; k < NK; k++) {
        CP_WAIT2();
        __syncthreads();
        uint32_t sa = sbase + (k % NSTAGE) * STAGE_BYTES;
        uint32_t sb = sa + A_BYTES;

#pragma unroll
        for (int ks = 0; ks < 4; ks++) {
            uint32_t a[4][4], b[4][4];
#pragma unroll
            for (int mi = 0; mi < 4; mi++) {
                int row = wm * 64 + mi * 16 + rlane;
                ldsm_x4(a[mi][0], a[mi][1], a[mi][2], a[mi][3],
                        sa + sw128((uint32_t)(row * 128 + ks * 32 + chalf)));
            }
#pragma unroll
            for (int ng = 0; ng < 4; ng++) {
                int row = wn * 64 + ng * 16 + rlane;
                ldsm_x4(b[ng][0], b[ng][1], b[ng][2], b[ng][3],
                        sb + sw128((uint32_t)(row * 128 + ks * 32 + chalf)));
            }
#pragma unroll
            for (int mi = 0; mi < 4; mi++)
#pragma unroll
                for (int ng = 0; ng < 4; ng++) {
                    mma_f16(acc[mi][ng * 2 + 0], a[mi], b[ng][0], b[ng][2]);
                    mma_f16(acc[mi][ng * 2 + 1], a[mi], b[ng][1], b[ng][3]);
                }
        }
        __syncthreads();
        if (k + NSTAGE < NK) {
            load_chunk(k + NSTAGE, sa, sb, m0, n0, tid);
        }
        CP_COMMIT();   // unconditional: pending-group count stays fixed
    }

    // ---- epilogue: fold scales, rowsum correction, bias -------------------
    const float2 sc = g_scale;
    const float ws = sc.x, alpha0 = sc.y;

    const int rm = m0 + wm * 64;
    const int cn = n0 + wn * 64;
    float fb[16];
#pragma unroll
    for (int jn = 0; jn < 8; jn++) {
        int col = cn + jn * 8 + (lid & 3) * 2;
        float2 b2 = *(const float2*)&g_biasf[col];
        fb[jn * 2] = b2.x; fb[jn * 2 + 1] = b2.y;
    }
#pragma unroll
    for (int mi = 0; mi < 4; mi++) {
        int r0 = rm + mi * 16 + (lid >> 2);
        float radd0 = alpha0 * g_rowsum[r0];
        float radd1 = alpha0 * g_rowsum[r0 + 8];
#pragma unroll
        for (int jn = 0; jn < 8; jn++) {
            int col = cn + jn * 8 + (lid & 3) * 2;
            const float* c = acc[mi][jn];
            float2 o0, o1;
            o0.x = ws * c[0] + radd0 + fb[jn * 2];
            o0.y = ws * c[1] + radd0 + fb[jn * 2 + 1];
            o1.x = ws * c[2] + radd1 + fb[jn * 2];
            o1.y = ws * c[3] + radd1 + fb[jn * 2 + 1];
            *(float2*)&out[(size_t)r0 * OUT_F + col] = o0;
            *(float2*)&out[(size_t)(r0 + 8) * OUT_F + col] = o1;
        }
    }
}

// ---------------- launch ----------------------------------------------------
extern "C" void kernel_launch(void* const* d_in, const int* in_sizes, int n_in,
                              void* d_out, int out_size) {
    const float* x    = (const float*)d_in[0];
    const int*   wq   = (const int*)d_in[1];
    const int*   bq   = (const int*)d_in[2];
    const float* wmin = (const float*)d_in[3];
    const float* wmax = (const float*)d_in[4];
    const float* bmin = (const float*)d_in[5];
    const float* bmax = (const float*)d_in[6];
    float* out = (float*)d_out;

    cudaFuncSetAttribute(k_gemm, cudaFuncAttributeMaxDynamicSharedMemorySize,
                         SMEM_TOTAL);

    k_prep<<<PREPW_BLKS + BATCH + 1, 256>>>(wq, x, bq, wmin, wmax,
                                            bmin, bmax);             // launch 1
    dim3 grid(OUT_F / TN, BATCH / TM);
    k_gemm<<<grid, 128, SMEM_TOTAL>>>(out);                          // launch 2
}